// round 12
// baseline (speedup 1.0000x reference)
#include <cuda_runtime.h>
#include <cuda_bf16.h>
#include <cstdint>

// Problem dims
#define N_INST 128
#define N_NOTES 88
#define BATCH 64
#define TLEN 201
#define FLEN 52
#define T2 197
#define F2 48
#define FEAT (T2 * F2)
#define KC 48
#define NCHUNK 197

// ---------------------------------------------------------------------------
// smem layout (per CTA, 2 CTAs/SM)
// ---------------------------------------------------------------------------
#define WF32_STAGE 16896                   // 88 rows x 192B fp32 W
#define WF32_OFF 0
#define WB_OFF (2 * WF32_STAGE)            // 33792: bf16 W hi/lo double buffer
#define WB_STAGE 24576
#define WLO_REL 12288
#define X_OFF (WB_OFF + 2 * WB_STAGE)      // 82944: X hi/lo double buffer (32 rows)
#define X_STAGE 8192
#define XLO_REL 4096
#define SMEM_TOTAL (X_OFF + 2 * X_STAGE)   // 99328

// ---------------------------------------------------------------------------
// helpers
// ---------------------------------------------------------------------------
__device__ __forceinline__ uint32_t smem_u32(const void* p) {
    uint32_t a;
    asm("{ .reg .u64 t; cvta.to.shared.u64 t, %1; cvt.u32.u64 %0, t; }" : "=r"(a) : "l"(p));
    return a;
}
__device__ __forceinline__ unsigned swz(unsigned off) { return off ^ ((off >> 3) & 0x70); }

__device__ __forceinline__ void cp16g(uint32_t dst, const void* src) {
    asm volatile("cp.async.cg.shared.global [%0], [%1], 16;" :: "r"(dst), "l"(src) : "memory");
}
__device__ __forceinline__ void cp_commit() { asm volatile("cp.async.commit_group;" ::: "memory"); }
#define CP_WAIT(n) asm volatile("cp.async.wait_group %0;" :: "n"(n) : "memory")

__device__ __forceinline__ void ldsm4(unsigned r[4], uint32_t a) {
    asm volatile("ldmatrix.sync.aligned.m8n8.x4.shared.b16 {%0,%1,%2,%3}, [%4];"
                 : "=r"(r[0]), "=r"(r[1]), "=r"(r[2]), "=r"(r[3]) : "r"(a));
}
__device__ __forceinline__ void ldsm2(unsigned r[2], uint32_t a) {
    asm volatile("ldmatrix.sync.aligned.m8n8.x2.shared.b16 {%0,%1}, [%2];"
                 : "=r"(r[0]), "=r"(r[1]) : "r"(a));
}
__device__ __forceinline__ void mma_bf16(float c[4], const unsigned a[4], const unsigned* b) {
    asm volatile(
        "mma.sync.aligned.m16n8k16.row.col.f32.bf16.bf16.f32 "
        "{%0,%1,%2,%3}, {%4,%5,%6,%7}, {%8,%9}, {%0,%1,%2,%3};"
        : "+f"(c[0]), "+f"(c[1]), "+f"(c[2]), "+f"(c[3])
        : "r"(a[0]), "r"(a[1]), "r"(a[2]), "r"(a[3]), "r"(b[0]), "r"(b[1]));
}
__device__ __forceinline__ unsigned cvt_bf16x2(float lo, float hi) {
    unsigned d;
    asm("cvt.rn.bf16x2.f32 %0, %1, %2;" : "=r"(d) : "f"(hi), "f"(lo));
    return d;
}
__device__ __forceinline__ void sts128(uint32_t a, unsigned r0, unsigned r1, unsigned r2, unsigned r3) {
    asm volatile("st.shared.v4.b32 [%0], {%1,%2,%3,%4};" :: "r"(a), "r"(r0), "r"(r1), "r"(r2), "r"(r3) : "memory");
}

// ---------------------------------------------------------------------------
// Producer conv iteration (accumulate-on-arrival, R10-proven math).
// ---------------------------------------------------------------------------
template <int S0, int S1, int S2>
__device__ __forceinline__ void conv_iter(
    int r, bool do_c2, bool emit,
    float (&ca)[3][10], float (&u)[3][8],
    const float* __restrict__ dptr,
    const float* W1, const float* W2, float B1, float B2,
    unsigned (&hi)[4], unsigned (&lo)[4])
{
    const float* rp = dptr + (size_t)r * FLEN;
    float4 A = *(const float4*)rp;
    float4 Bv = *(const float4*)(rp + 4);
    float4 Cv = *(const float4*)(rp + 8);
    float d[12] = {A.x, A.y, A.z, A.w, Bv.x, Bv.y, Bv.z, Bv.w, Cv.x, Cv.y, Cv.z, Cv.w};

#pragma unroll
    for (int j = 0; j < 10; ++j) {
        ca[S0][j] = fmaf(W1[2], d[j + 2], fmaf(W1[1], d[j + 1], fmaf(W1[0], d[j], B1)));
        ca[S1][j] = fmaf(W1[5], d[j + 2], fmaf(W1[4], d[j + 1], fmaf(W1[3], d[j], ca[S1][j])));
        ca[S2][j] = fmaf(W1[8], d[j + 2], fmaf(W1[7], d[j + 1], fmaf(W1[6], d[j], ca[S2][j])));
    }
    if (do_c2) {
        float g[10];
#pragma unroll
        for (int j = 0; j < 10; ++j) g[j] = fmaxf(ca[S2][j], 0.f);
#pragma unroll
        for (int j = 0; j < 8; ++j) {
            u[S2][j] = fmaf(W2[2], g[j + 2], fmaf(W2[1], g[j + 1], fmaf(W2[0], g[j], B2)));
            u[S0][j] = fmaf(W2[5], g[j + 2], fmaf(W2[4], g[j + 1], fmaf(W2[3], g[j], u[S0][j])));
            u[S1][j] = fmaf(W2[8], g[j + 2], fmaf(W2[7], g[j + 1], fmaf(W2[6], g[j], u[S1][j])));
        }
        if (emit) {
#pragma unroll
            for (int q = 0; q < 4; ++q) {
                float h0 = fmaxf(u[S1][2 * q], 0.f);
                float h1 = fmaxf(u[S1][2 * q + 1], 0.f);
                unsigned ub0 = __float_as_uint(h0), ub1 = __float_as_uint(h1);
                hi[q] = __byte_perm(ub0, ub1, 0x7632);
                float r0 = h0 - __uint_as_float(ub0 & 0xffff0000u);
                float r1 = h1 - __uint_as_float(ub1 & 0xffff0000u);
                lo[q] = cvt_bf16x2(r0, r1);
            }
        }
    }
}

// ---------------------------------------------------------------------------
// Fused kernel: 2 CTAs per instrument (half-batch each), 320 threads.
// Warps 0-3: MMA consumers (tile 32x24). Warps 4-9: conv producers.
// ---------------------------------------------------------------------------
__global__ __launch_bounds__(320, 2) void fused_kernel(
    const float* __restrict__ data,
    const float* __restrict__ w1, const float* __restrict__ b1,
    const float* __restrict__ w2, const float* __restrict__ b2,
    const float* __restrict__ wfc,
    const float* __restrict__ bfc,
    float* __restrict__ out)
{
    extern __shared__ char sm[];
    const uint32_t sbase = smem_u32(sm);
    const int i = blockIdx.x >> 1;
    const int half = blockIdx.x & 1;
    const int tid = threadIdx.x;
    const int lane = tid & 31;
    const int wid = tid >> 5;

    // zero bf16-W buffers (pad note rows 88..95 stay zero forever)
    for (int o = tid * 16; o < 2 * WB_STAGE; o += 320 * 16)
        *(uint4*)(sm + WB_OFF + o) = make_uint4(0, 0, 0, 0);
    __syncthreads();

    const float* Wp = wfc + (size_t)i * N_NOTES * FEAT;

    // ---- shared W pipeline (all 320 threads) ----
    auto prefetchW = [&](int c) {
        const int k0 = c * KC;
        const uint32_t wdst = sbase + WF32_OFF + (c & 1) * WF32_STAGE;
#pragma unroll
        for (int s = 0; s < 4; ++s) {
            int idx = tid + s * 320;
            if (idx < 1056)
                cp16g(wdst + idx * 16, Wp + (size_t)(idx / 12) * FEAT + k0 + (idx % 12) * 4);
        }
        cp_commit();
    };
    auto convertW = [&](int c) {
        const char* src = sm + WF32_OFF + (c & 1) * WF32_STAGE;
        char* dhi = sm + WB_OFF + (c & 1) * WB_STAGE;
        char* dlo = dhi + WLO_REL;
#pragma unroll
        for (int s = 0; s < 4; ++s) {
            int idx = tid + s * 320;
            if (idx < 1056) {
                int row = idx / 12, q = idx % 12;
                float4 v = *(const float4*)(src + idx * 16);
                unsigned ax = __float_as_uint(v.x), ay = __float_as_uint(v.y);
                unsigned az = __float_as_uint(v.z), aw = __float_as_uint(v.w);
                unsigned hi0 = __byte_perm(ax, ay, 0x7632);
                unsigned hi1 = __byte_perm(az, aw, 0x7632);
                float rx = v.x - __uint_as_float(ax & 0xffff0000u);
                float ry = v.y - __uint_as_float(ay & 0xffff0000u);
                float rz = v.z - __uint_as_float(az & 0xffff0000u);
                float rw = v.w - __uint_as_float(aw & 0xffff0000u);
                unsigned lo0 = cvt_bf16x2(rx, ry);
                unsigned lo1 = cvt_bf16x2(rz, rw);
                unsigned off = swz(row * 128 + q * 8);
                *(uint2*)(dhi + off) = make_uint2(hi0, hi1);
                *(uint2*)(dlo + off) = make_uint2(lo0, lo1);
            }
        }
    };

    if (tid < 128) {
        // ================= CONSUMERS (warps 0-3) =================
        const int n0 = wid * 24;
        float acc[2][3][4];
#pragma unroll
        for (int mt = 0; mt < 2; ++mt)
#pragma unroll
            for (int nt = 0; nt < 3; ++nt)
#pragma unroll
                for (int r = 0; r < 4; ++r) acc[mt][nt][r] = 0.f;

        const int a_row = lane & 15;
        const int a_colb = (lane >> 4) << 4;
        const int b4_row = (lane & 7) + ((lane >> 4) << 3);
        const int b4_colb = ((lane >> 3) & 1) << 4;
        const int b2_row = lane & 7;
        const int b2_colb = ((lane >> 3) & 1) << 4;

        prefetchW(0);

        for (int c = 0; c < NCHUNK; ++c) {
            if (c + 1 < NCHUNK) { prefetchW(c + 1); CP_WAIT(1); }
            else { CP_WAIT(0); }
            convertW(c);
            __syncthreads();

            const uint32_t xb = sbase + X_OFF + (c & 1) * X_STAGE;
            const uint32_t wb = sbase + WB_OFF + (c & 1) * WB_STAGE;
#pragma unroll
            for (int ks = 0; ks < 3; ++ks) {
                const int kb = ks * 32;
                unsigned bh[3][2], bl[3][2];
                unsigned off4 = swz((n0 + b4_row) * 128 + kb + b4_colb);
                ldsm4(&bh[0][0], wb + off4);
                ldsm4(&bl[0][0], wb + WLO_REL + off4);
                unsigned off2 = swz((n0 + 16 + b2_row) * 128 + kb + b2_colb);
                ldsm2(bh[2], wb + off2);
                ldsm2(bl[2], wb + WLO_REL + off2);
#pragma unroll
                for (int mt = 0; mt < 2; ++mt) {
                    unsigned ahi[4], alo[4];
                    unsigned offA = swz((mt * 16 + a_row) * 128 + kb + a_colb);
                    ldsm4(ahi, xb + offA);
                    ldsm4(alo, xb + XLO_REL + offA);
#pragma unroll
                    for (int nt = 0; nt < 3; ++nt) {
                        mma_bf16(acc[mt][nt], ahi, bh[nt]);
                        mma_bf16(acc[mt][nt], ahi, bl[nt]);
                        mma_bf16(acc[mt][nt], alo, bh[nt]);
                    }
                }
            }
        }

        // epilogue: bias + sigmoid + store out[b][i][n]
#pragma unroll
        for (int mt = 0; mt < 2; ++mt) {
            int b0 = half * 32 + mt * 16 + (lane >> 2);
#pragma unroll
            for (int nt = 0; nt < 3; ++nt) {
                int n = n0 + nt * 8 + 2 * (lane & 3);
                if (n < N_NOTES) {
                    float bi0 = bfc[i * N_NOTES + n];
                    float bi1 = bfc[i * N_NOTES + n + 1];
                    float s0 = acc[mt][nt][0] + bi0;
                    float s1 = acc[mt][nt][1] + bi1;
                    float s2 = acc[mt][nt][2] + bi0;
                    float s3 = acc[mt][nt][3] + bi1;
                    float2 r0 = make_float2(1.f / (1.f + __expf(-s0)), 1.f / (1.f + __expf(-s1)));
                    float2 r1 = make_float2(1.f / (1.f + __expf(-s2)), 1.f / (1.f + __expf(-s3)));
                    *(float2*)(out + ((size_t)b0 * N_INST + i) * N_NOTES + n) = r0;
                    *(float2*)(out + ((size_t)(b0 + 8) * N_INST + i) * N_NOTES + n) = r1;
                }
            }
        }
    } else {
        // ================= PRODUCERS (warps 4-9) =================
        const int ptid = tid - 128;     // 0..191
        const int s = ptid % 6;         // strip: output cols 8s..8s+7
        const int bl = ptid / 6;        // local batch 0..31
        const int b = half * 32 + bl;

        float W1[9], W2[9];
#pragma unroll
        for (int k = 0; k < 9; ++k) { W1[k] = w1[i * 9 + k]; W2[k] = w2[i * 9 + k]; }
        const float B1 = b1[i], B2 = b2[i];

        const float* dptr = data + (size_t)b * TLEN * FLEN + 8 * s;
        const unsigned xoff = swz(bl * 128 + s * 16);

        float ca[3][10], u[3][8];
#pragma unroll
        for (int k = 0; k < 3; ++k) {
#pragma unroll
            for (int j = 0; j < 10; ++j) ca[k][j] = 0.f;
#pragma unroll
            for (int j = 0; j < 8; ++j) u[k][j] = 0.f;
        }
        unsigned hi[4], lo[4];

        auto xstore = [&](int buf) {
            uint32_t xa = sbase + X_OFF + buf * X_STAGE;
            sts128(xa + xoff, hi[0], hi[1], hi[2], hi[3]);
            sts128(xa + XLO_REL + xoff, lo[0], lo[1], lo[2], lo[3]);
        };

        prefetchW(0);
        // prologue conv: rows 0..4; conv2 row 0 completes at r=4 -> X buf 0
        conv_iter<0, 2, 1>(0, false, false, ca, u, dptr, W1, W2, B1, B2, hi, lo);
        conv_iter<1, 0, 2>(1, false, false, ca, u, dptr, W1, W2, B1, B2, hi, lo);
        conv_iter<2, 1, 0>(2, true,  false, ca, u, dptr, W1, W2, B1, B2, hi, lo);
        conv_iter<0, 2, 1>(3, true,  false, ca, u, dptr, W1, W2, B1, B2, hi, lo);
        conv_iter<1, 0, 2>(4, true,  true,  ca, u, dptr, W1, W2, B1, B2, hi, lo);
        xstore(0);

#define PBODY(c, S0, S1, S2) do { \
    if ((c) + 1 < NCHUNK) { prefetchW((c) + 1); CP_WAIT(1); } \
    else { CP_WAIT(0); } \
    convertW(c); \
    if ((c) + 1 < NCHUNK) \
        conv_iter<S0, S1, S2>((c) + 5, true, true, ca, u, dptr, W1, W2, B1, B2, hi, lo); \
    __syncthreads(); \
    if ((c) + 1 < NCHUNK) xstore(((c) + 1) & 1); \
} while (0)

        for (int c0 = 0; c0 < 195; c0 += 3) {
            PBODY(c0 + 0, 2, 1, 0);
            PBODY(c0 + 1, 0, 2, 1);
            PBODY(c0 + 2, 1, 0, 2);
        }
        PBODY(195, 2, 1, 0);
        PBODY(196, 0, 2, 1);
#undef PBODY
    }
}

// ---------------------------------------------------------------------------
extern "C" void kernel_launch(void* const* d_in, const int* in_sizes, int n_in,
                              void* d_out, int out_size)
{
    const float* data = (const float*)d_in[0];
    const float* w1   = (const float*)d_in[1];
    const float* b1   = (const float*)d_in[2];
    const float* w2   = (const float*)d_in[3];
    const float* b2   = (const float*)d_in[4];
    const float* wfc  = (const float*)d_in[5];
    const float* bfc  = (const float*)d_in[6];
    float* out = (float*)d_out;

    cudaFuncSetAttribute(fused_kernel, cudaFuncAttributeMaxDynamicSharedMemorySize, SMEM_TOTAL);
    fused_kernel<<<2 * N_INST, 320, SMEM_TOTAL>>>(data, w1, b1, w2, b2, wfc, bfc, out);
}

// round 13
// speedup vs baseline: 1.0001x; 1.0001x over previous
#include <cuda_runtime.h>
#include <cuda_bf16.h>
#include <cstdint>

// Problem dims
#define N_INST 128
#define N_NOTES 88
#define BATCH 64
#define TLEN 201
#define FLEN 52
#define T2 197
#define F2 48
#define FEAT (T2 * F2)
#define KC 48
#define NCHUNK 197
#define NTHREADS 640

// ---------------------------------------------------------------------------
// smem layout (R10-identical)
// ---------------------------------------------------------------------------
#define WF32_STAGE 16896                   // 88 rows x 192B fp32 W
#define WF32_OFF 0
#define WB_OFF (4 * WF32_STAGE)            // 67584: bf16 W hi/lo double buffer
#define WB_STAGE 24576
#define WLO_REL 12288
#define X_OFF (WB_OFF + 2 * WB_STAGE)      // 116736: X hi/lo double buffer
#define X_STAGE 16384
#define XLO_REL 8192
#define SMEM_TOTAL (X_OFF + 2 * X_STAGE)   // 149504

// ---------------------------------------------------------------------------
// helpers
// ---------------------------------------------------------------------------
__device__ __forceinline__ uint32_t smem_u32(const void* p) {
    uint32_t a;
    asm("{ .reg .u64 t; cvta.to.shared.u64 t, %1; cvt.u32.u64 %0, t; }" : "=r"(a) : "l"(p));
    return a;
}
__device__ __forceinline__ unsigned swz(unsigned off) { return off ^ ((off >> 3) & 0x70); }

__device__ __forceinline__ void cp16g(uint32_t dst, const void* src) {
    asm volatile("cp.async.cg.shared.global [%0], [%1], 16;" :: "r"(dst), "l"(src) : "memory");
}
__device__ __forceinline__ void cp_commit() { asm volatile("cp.async.commit_group;" ::: "memory"); }
#define CP_WAIT(n) asm volatile("cp.async.wait_group %0;" :: "n"(n) : "memory")
#define TAILWAIT(c) do { \
    if ((c) < NCHUNK - 3)       { CP_WAIT(2); } \
    else if ((c) == NCHUNK - 3) { CP_WAIT(1); } \
    else                        { CP_WAIT(0); } \
} while (0)

__device__ __forceinline__ void ldsm4(unsigned r[4], uint32_t a) {
    asm volatile("ldmatrix.sync.aligned.m8n8.x4.shared.b16 {%0,%1,%2,%3}, [%4];"
                 : "=r"(r[0]), "=r"(r[1]), "=r"(r[2]), "=r"(r[3]) : "r"(a));
}
__device__ __forceinline__ void ldsm2(unsigned r[2], uint32_t a) {
    asm volatile("ldmatrix.sync.aligned.m8n8.x2.shared.b16 {%0,%1}, [%2];"
                 : "=r"(r[0]), "=r"(r[1]) : "r"(a));
}
__device__ __forceinline__ void mma_bf16(float c[4], const unsigned a[4], const unsigned* b) {
    asm volatile(
        "mma.sync.aligned.m16n8k16.row.col.f32.bf16.bf16.f32 "
        "{%0,%1,%2,%3}, {%4,%5,%6,%7}, {%8,%9}, {%0,%1,%2,%3};"
        : "+f"(c[0]), "+f"(c[1]), "+f"(c[2]), "+f"(c[3])
        : "r"(a[0]), "r"(a[1]), "r"(a[2]), "r"(a[3]), "r"(b[0]), "r"(b[1]));
}
__device__ __forceinline__ unsigned cvt_bf16x2(float lo, float hi) {
    unsigned d;
    asm("cvt.rn.bf16x2.f32 %0, %1, %2;" : "=r"(d) : "f"(hi), "f"(lo));
    return d;
}
__device__ __forceinline__ void sts128(uint32_t a, unsigned r0, unsigned r1, unsigned r2, unsigned r3) {
    asm volatile("st.shared.v4.b32 [%0], {%1,%2,%3,%4};" :: "r"(a), "r"(r0), "r"(r1), "r"(r2), "r"(r3) : "memory");
}

// ---------------------------------------------------------------------------
// Producer conv iteration (accumulate-on-arrival, R10-proven math).
// ---------------------------------------------------------------------------
template <int S0, int S1, int S2>
__device__ __forceinline__ void conv_iter(
    int r, bool do_c2, bool emit,
    float (&ca)[3][10], float (&u)[3][8],
    const float* __restrict__ dptr,
    const float* W1, const float* W2, float B1, float B2,
    unsigned (&hi)[4], unsigned (&lo)[4])
{
    const float* rp = dptr + (size_t)r * FLEN;
    float4 A = *(const float4*)rp;
    float4 Bv = *(const float4*)(rp + 4);
    float4 Cv = *(const float4*)(rp + 8);
    float d[12] = {A.x, A.y, A.z, A.w, Bv.x, Bv.y, Bv.z, Bv.w, Cv.x, Cv.y, Cv.z, Cv.w};

#pragma unroll
    for (int j = 0; j < 10; ++j) {
        ca[S0][j] = fmaf(W1[2], d[j + 2], fmaf(W1[1], d[j + 1], fmaf(W1[0], d[j], B1)));
        ca[S1][j] = fmaf(W1[5], d[j + 2], fmaf(W1[4], d[j + 1], fmaf(W1[3], d[j], ca[S1][j])));
        ca[S2][j] = fmaf(W1[8], d[j + 2], fmaf(W1[7], d[j + 1], fmaf(W1[6], d[j], ca[S2][j])));
    }
    if (do_c2) {
        float g[10];
#pragma unroll
        for (int j = 0; j < 10; ++j) g[j] = fmaxf(ca[S2][j], 0.f);
#pragma unroll
        for (int j = 0; j < 8; ++j) {
            u[S2][j] = fmaf(W2[2], g[j + 2], fmaf(W2[1], g[j + 1], fmaf(W2[0], g[j], B2)));
            u[S0][j] = fmaf(W2[5], g[j + 2], fmaf(W2[4], g[j + 1], fmaf(W2[3], g[j], u[S0][j])));
            u[S1][j] = fmaf(W2[8], g[j + 2], fmaf(W2[7], g[j + 1], fmaf(W2[6], g[j], u[S1][j])));
        }
        if (emit) {
#pragma unroll
            for (int q = 0; q < 4; ++q) {
                float h0 = fmaxf(u[S1][2 * q], 0.f);
                float h1 = fmaxf(u[S1][2 * q + 1], 0.f);
                unsigned ub0 = __float_as_uint(h0), ub1 = __float_as_uint(h1);
                hi[q] = __byte_perm(ub0, ub1, 0x7632);
                float r0 = h0 - __uint_as_float(ub0 & 0xffff0000u);
                float r1 = h1 - __uint_as_float(ub1 & 0xffff0000u);
                lo[q] = cvt_bf16x2(r0, r1);
            }
        }
    }
}

// ---------------------------------------------------------------------------
// Fused kernel: one CTA / instrument, 640 threads.
// Warps 0-7: MMA consumers (2 per SMSP, warp tile 32x24).
// Warps 8-19: conv producers (R10-proven).
// ---------------------------------------------------------------------------
__global__ __launch_bounds__(NTHREADS, 1) void fused_kernel(
    const float* __restrict__ data,
    const float* __restrict__ w1, const float* __restrict__ b1,
    const float* __restrict__ w2, const float* __restrict__ b2,
    const float* __restrict__ wfc,
    const float* __restrict__ bfc,
    float* __restrict__ out)
{
    extern __shared__ char sm[];
    const uint32_t sbase = smem_u32(sm);
    const int i = blockIdx.x;
    const int tid = threadIdx.x;
    const int lane = tid & 31;
    const int wid = tid >> 5;

    // zero bf16-W buffers (pad note rows 88..95 stay zero forever)
    for (int o = tid * 16; o < 2 * WB_STAGE; o += NTHREADS * 16)
        *(uint4*)(sm + WB_OFF + o) = make_uint4(0, 0, 0, 0);

    const float* Wp = wfc + (size_t)i * N_NOTES * FEAT;

    // ---- shared W pipeline (all 640 threads take their share) ----
    auto prefetchW = [&](int c) {
        const int k0 = c * KC;
        const uint32_t wdst = sbase + WF32_OFF + (c & 3) * WF32_STAGE;
#pragma unroll
        for (int s = 0; s < 2; ++s) {
            int idx = tid + s * NTHREADS;
            if (idx < 1056)
                cp16g(wdst + idx * 16, Wp + (size_t)(idx / 12) * FEAT + k0 + (idx % 12) * 4);
        }
        cp_commit();
    };
    auto convertW = [&](int c) {
        const char* src = sm + WF32_OFF + (c & 3) * WF32_STAGE;
        char* dhi = sm + WB_OFF + (c & 1) * WB_STAGE;
        char* dlo = dhi + WLO_REL;
#pragma unroll
        for (int s = 0; s < 2; ++s) {
            int idx = tid + s * NTHREADS;
            if (idx < 1056) {
                int row = idx / 12, q = idx % 12;
                float4 v = *(const float4*)(src + idx * 16);
                unsigned ax = __float_as_uint(v.x), ay = __float_as_uint(v.y);
                unsigned az = __float_as_uint(v.z), aw = __float_as_uint(v.w);
                unsigned hi0 = __byte_perm(ax, ay, 0x7632);
                unsigned hi1 = __byte_perm(az, aw, 0x7632);
                float rx = v.x - __uint_as_float(ax & 0xffff0000u);
                float ry = v.y - __uint_as_float(ay & 0xffff0000u);
                float rz = v.z - __uint_as_float(az & 0xffff0000u);
                float rw = v.w - __uint_as_float(aw & 0xffff0000u);
                unsigned lo0 = cvt_bf16x2(rx, ry);
                unsigned lo1 = cvt_bf16x2(rz, rw);
                unsigned off = swz(row * 128 + q * 8);
                *(uint2*)(dhi + off) = make_uint2(hi0, hi1);
                *(uint2*)(dlo + off) = make_uint2(lo0, lo1);
            }
        }
    };

    if (tid < 256) {
        // ================= CONSUMERS (warps 0-7) =================
        const int warp_n = wid & 3;       // note column group
        const int warp_m = wid >> 2;      // batch half (0: rows 0-31, 1: rows 32-63)
        const int n0 = warp_n * 24;
        float acc[2][3][4];
#pragma unroll
        for (int mt = 0; mt < 2; ++mt)
#pragma unroll
            for (int nt = 0; nt < 3; ++nt)
#pragma unroll
                for (int r = 0; r < 4; ++r) acc[mt][nt][r] = 0.f;

        const int a_row = lane & 15;
        const int a_colb = (lane >> 4) << 4;
        const int b4_row = (lane & 7) + ((lane >> 4) << 3);
        const int b4_colb = ((lane >> 3) & 1) << 4;
        const int b2_row = lane & 7;
        const int b2_colb = ((lane >> 3) & 1) << 4;

        prefetchW(0); prefetchW(1); prefetchW(2);
        CP_WAIT(2);
        __syncthreads();
        convertW(0);

        for (int c = 0; c < NCHUNK; ++c) {
            if (c + 3 < NCHUNK) prefetchW(c + 3);
            TAILWAIT(c);
            __syncthreads();
            if (c + 1 < NCHUNK) convertW(c + 1);

            const uint32_t xb = sbase + X_OFF + (c & 1) * X_STAGE;
            const uint32_t wb = sbase + WB_OFF + (c & 1) * WB_STAGE;
#pragma unroll
            for (int ks = 0; ks < 3; ++ks) {
                const int kb = ks * 32;
                unsigned bh[3][2], bl[3][2];
                unsigned off4 = swz((n0 + b4_row) * 128 + kb + b4_colb);
                ldsm4(&bh[0][0], wb + off4);
                ldsm4(&bl[0][0], wb + WLO_REL + off4);
                unsigned off2 = swz((n0 + 16 + b2_row) * 128 + kb + b2_colb);
                ldsm2(bh[2], wb + off2);
                ldsm2(bl[2], wb + WLO_REL + off2);
#pragma unroll
                for (int mt = 0; mt < 2; ++mt) {
                    unsigned ahi[4], alo[4];
                    unsigned offA = swz(((warp_m * 2 + mt) * 16 + a_row) * 128 + kb + a_colb);
                    ldsm4(ahi, xb + offA);
                    ldsm4(alo, xb + XLO_REL + offA);
#pragma unroll
                    for (int nt = 0; nt < 3; ++nt) {
                        mma_bf16(acc[mt][nt], ahi, bh[nt]);
                        mma_bf16(acc[mt][nt], ahi, bl[nt]);
                        mma_bf16(acc[mt][nt], alo, bh[nt]);
                    }
                }
            }
        }

        // epilogue: bias + sigmoid + store out[b][i][n]
#pragma unroll
        for (int mt = 0; mt < 2; ++mt) {
            int b0 = (warp_m * 2 + mt) * 16 + (lane >> 2);
#pragma unroll
            for (int nt = 0; nt < 3; ++nt) {
                int n = n0 + nt * 8 + 2 * (lane & 3);
                if (n < N_NOTES) {
                    float bi0 = bfc[i * N_NOTES + n];
                    float bi1 = bfc[i * N_NOTES + n + 1];
                    float s0 = acc[mt][nt][0] + bi0;
                    float s1 = acc[mt][nt][1] + bi1;
                    float s2 = acc[mt][nt][2] + bi0;
                    float s3 = acc[mt][nt][3] + bi1;
                    float2 r0 = make_float2(1.f / (1.f + __expf(-s0)), 1.f / (1.f + __expf(-s1)));
                    float2 r1 = make_float2(1.f / (1.f + __expf(-s2)), 1.f / (1.f + __expf(-s3)));
                    *(float2*)(out + ((size_t)b0 * N_INST + i) * N_NOTES + n) = r0;
                    *(float2*)(out + ((size_t)(b0 + 8) * N_INST + i) * N_NOTES + n) = r1;
                }
            }
        }
    } else {
        // ================= PRODUCERS (warps 8-19) =================
        const int ptid = tid - 256;     // 0..383
        const int s = ptid % 6;         // strip: output cols 8s..8s+7
        const int b = ptid / 6;         // batch 0..63

        float W1[9], W2[9];
#pragma unroll
        for (int k = 0; k < 9; ++k) { W1[k] = w1[i * 9 + k]; W2[k] = w2[i * 9 + k]; }
        const float B1 = b1[i], B2 = b2[i];

        const float* dptr = data + (size_t)b * TLEN * FLEN + 8 * s;
        const unsigned xoff = swz(b * 128 + s * 16);

        float ca[3][10], u[3][8];
#pragma unroll
        for (int k = 0; k < 3; ++k) {
#pragma unroll
            for (int j = 0; j < 10; ++j) ca[k][j] = 0.f;
#pragma unroll
            for (int j = 0; j < 8; ++j) u[k][j] = 0.f;
        }
        unsigned hi[4], lo[4];

        auto xstore = [&](int buf) {
            uint32_t xa = sbase + X_OFF + buf * X_STAGE;
            sts128(xa + xoff, hi[0], hi[1], hi[2], hi[3]);
            sts128(xa + XLO_REL + xoff, lo[0], lo[1], lo[2], lo[3]);
        };

        prefetchW(0); prefetchW(1); prefetchW(2);
        // prologue conv: rows 0..4; conv2 row 0 completes at r=4 -> X buf 0
        conv_iter<0, 2, 1>(0, false, false, ca, u, dptr, W1, W2, B1, B2, hi, lo);
        conv_iter<1, 0, 2>(1, false, false, ca, u, dptr, W1, W2, B1, B2, hi, lo);
        conv_iter<2, 1, 0>(2, true,  false, ca, u, dptr, W1, W2, B1, B2, hi, lo);
        conv_iter<0, 2, 1>(3, true,  false, ca, u, dptr, W1, W2, B1, B2, hi, lo);
        conv_iter<1, 0, 2>(4, true,  true,  ca, u, dptr, W1, W2, B1, B2, hi, lo);
        xstore(0);
        CP_WAIT(2);
        __syncthreads();
        convertW(0);

#define PBODY(c, S0, S1, S2) do { \
    if ((c) + 3 < NCHUNK) prefetchW((c) + 3); \
    conv_iter<S0, S1, S2>((c) + 5, true, true, ca, u, dptr, W1, W2, B1, B2, hi, lo); \
    TAILWAIT(c); \
    __syncthreads(); \
    if ((c) + 1 < NCHUNK) convertW((c) + 1); \
    xstore(((c) + 1) & 1); \
} while (0)

        for (int c0 = 0; c0 < 195; c0 += 3) {
            PBODY(c0 + 0, 2, 1, 0);
            PBODY(c0 + 1, 0, 2, 1);
            PBODY(c0 + 2, 1, 0, 2);
        }
        PBODY(195, 2, 1, 0);
#undef PBODY
        // final chunk c=196: no conv, no convert
        {
            CP_WAIT(0);
            __syncthreads();
        }
    }
}

// ---------------------------------------------------------------------------
extern "C" void kernel_launch(void* const* d_in, const int* in_sizes, int n_in,
                              void* d_out, int out_size)
{
    const float* data = (const float*)d_in[0];
    const float* w1   = (const float*)d_in[1];
    const float* b1   = (const float*)d_in[2];
    const float* w2   = (const float*)d_in[3];
    const float* b2   = (const float*)d_in[4];
    const float* wfc  = (const float*)d_in[5];
    const float* bfc  = (const float*)d_in[6];
    float* out = (float*)d_out;

    cudaFuncSetAttribute(fused_kernel, cudaFuncAttributeMaxDynamicSharedMemorySize, SMEM_TOTAL);
    fused_kernel<<<N_INST, NTHREADS, SMEM_TOTAL>>>(data, w1, b1, w2, b2, wfc, bfc, out);
}

// round 14
// speedup vs baseline: 1.0605x; 1.0604x over previous
#include <cuda_runtime.h>
#include <cuda_bf16.h>
#include <cstdint>

// Problem dims
#define N_INST 128
#define N_NOTES 88
#define BATCH 64
#define TLEN 201
#define FLEN 52
#define T2 197
#define F2 48
#define FEAT (T2 * F2)
#define KC 48
#define NCHUNK 197
#define NTHREADS 640

// Named barrier ids
#define FB0 1   // full: X[s] + W f32 chunk ready (producers arrive, consumers sync)
#define EB0 5   // empty: X[s] consumed (consumers arrive, producers sync)
#define WD0 9   // W f32 stage converted (consumers arrive, producers sync)
#define CBID 13 // consumer-only barrier

// ---------------------------------------------------------------------------
// smem layout
// ---------------------------------------------------------------------------
#define WF32_STAGE 16896                   // 88 rows x 192B fp32 W
#define WF32_OFF 0                         // 4-stage ring
#define WB_OFF (4 * WF32_STAGE)            // 67584: bf16 W hi/lo double buffer
#define WB_STAGE 24576
#define WLO_REL 12288
#define X_OFF (WB_OFF + 2 * WB_STAGE)      // 116736: X hi/lo 4-stage ring
#define X_STAGE 16384
#define XLO_REL 8192
#define SMEM_TOTAL (X_OFF + 4 * X_STAGE)   // 182272

// ---------------------------------------------------------------------------
// helpers
// ---------------------------------------------------------------------------
__device__ __forceinline__ uint32_t smem_u32(const void* p) {
    uint32_t a;
    asm("{ .reg .u64 t; cvta.to.shared.u64 t, %1; cvt.u32.u64 %0, t; }" : "=r"(a) : "l"(p));
    return a;
}
__device__ __forceinline__ unsigned swz(unsigned off) { return off ^ ((off >> 3) & 0x70); }

__device__ __forceinline__ void cp16g(uint32_t dst, const void* src) {
    asm volatile("cp.async.cg.shared.global [%0], [%1], 16;" :: "r"(dst), "l"(src) : "memory");
}
__device__ __forceinline__ void cp_commit() { asm volatile("cp.async.commit_group;" ::: "memory"); }
#define CP_WAIT(n) asm volatile("cp.async.wait_group %0;" :: "n"(n) : "memory")

#define BAR_SYNC(id, cnt)   asm volatile("bar.sync %0, %1;"   :: "r"(id), "r"(cnt) : "memory")
#define BAR_ARRIVE(id, cnt) asm volatile("bar.arrive %0, %1;" :: "r"(id), "r"(cnt) : "memory")
#define MEMBAR_CTA()        asm volatile("membar.cta;" ::: "memory")

__device__ __forceinline__ void ldsm4(unsigned r[4], uint32_t a) {
    asm volatile("ldmatrix.sync.aligned.m8n8.x4.shared.b16 {%0,%1,%2,%3}, [%4];"
                 : "=r"(r[0]), "=r"(r[1]), "=r"(r[2]), "=r"(r[3]) : "r"(a));
}
__device__ __forceinline__ void ldsm2(unsigned r[2], uint32_t a) {
    asm volatile("ldmatrix.sync.aligned.m8n8.x2.shared.b16 {%0,%1}, [%2];"
                 : "=r"(r[0]), "=r"(r[1]) : "r"(a));
}
__device__ __forceinline__ void mma_bf16(float c[4], const unsigned a[4], const unsigned* b) {
    asm volatile(
        "mma.sync.aligned.m16n8k16.row.col.f32.bf16.bf16.f32 "
        "{%0,%1,%2,%3}, {%4,%5,%6,%7}, {%8,%9}, {%0,%1,%2,%3};"
        : "+f"(c[0]), "+f"(c[1]), "+f"(c[2]), "+f"(c[3])
        : "r"(a[0]), "r"(a[1]), "r"(a[2]), "r"(a[3]), "r"(b[0]), "r"(b[1]));
}
__device__ __forceinline__ unsigned cvt_bf16x2(float lo, float hi) {
    unsigned d;
    asm("cvt.rn.bf16x2.f32 %0, %1, %2;" : "=r"(d) : "f"(hi), "f"(lo));
    return d;
}
__device__ __forceinline__ void sts128(uint32_t a, unsigned r0, unsigned r1, unsigned r2, unsigned r3) {
    asm volatile("st.shared.v4.b32 [%0], {%1,%2,%3,%4};" :: "r"(a), "r"(r0), "r"(r1), "r"(r2), "r"(r3) : "memory");
}

// ---------------------------------------------------------------------------
// Producer conv iteration (accumulate-on-arrival, R10-proven math).
// Slots: S0 = r%3 (assign), S1 = (r+2)%3, S2 = (r+1)%3 (conv1 completes).
// ---------------------------------------------------------------------------
template <int S0, int S1, int S2>
__device__ __forceinline__ void conv_iter(
    int r, bool do_c2, bool emit,
    float (&ca)[3][10], float (&u)[3][8],
    const float* __restrict__ dptr,
    const float* W1, const float* W2, float B1, float B2,
    unsigned (&hi)[4], unsigned (&lo)[4])
{
    const float* rp = dptr + (size_t)r * FLEN;
    float4 A = *(const float4*)rp;
    float4 Bv = *(const float4*)(rp + 4);
    float4 Cv = *(const float4*)(rp + 8);
    float d[12] = {A.x, A.y, A.z, A.w, Bv.x, Bv.y, Bv.z, Bv.w, Cv.x, Cv.y, Cv.z, Cv.w};

#pragma unroll
    for (int j = 0; j < 10; ++j) {
        ca[S0][j] = fmaf(W1[2], d[j + 2], fmaf(W1[1], d[j + 1], fmaf(W1[0], d[j], B1)));
        ca[S1][j] = fmaf(W1[5], d[j + 2], fmaf(W1[4], d[j + 1], fmaf(W1[3], d[j], ca[S1][j])));
        ca[S2][j] = fmaf(W1[8], d[j + 2], fmaf(W1[7], d[j + 1], fmaf(W1[6], d[j], ca[S2][j])));
    }
    if (do_c2) {
        float g[10];
#pragma unroll
        for (int j = 0; j < 10; ++j) g[j] = fmaxf(ca[S2][j], 0.f);
#pragma unroll
        for (int j = 0; j < 8; ++j) {
            u[S2][j] = fmaf(W2[2], g[j + 2], fmaf(W2[1], g[j + 1], fmaf(W2[0], g[j], B2)));
            u[S0][j] = fmaf(W2[5], g[j + 2], fmaf(W2[4], g[j + 1], fmaf(W2[3], g[j], u[S0][j])));
            u[S1][j] = fmaf(W2[8], g[j + 2], fmaf(W2[7], g[j + 1], fmaf(W2[6], g[j], u[S1][j])));
        }
        if (emit) {
#pragma unroll
            for (int q = 0; q < 4; ++q) {
                float h0 = fmaxf(u[S1][2 * q], 0.f);
                float h1 = fmaxf(u[S1][2 * q + 1], 0.f);
                unsigned ub0 = __float_as_uint(h0), ub1 = __float_as_uint(h1);
                hi[q] = __byte_perm(ub0, ub1, 0x7632);
                float r0 = h0 - __uint_as_float(ub0 & 0xffff0000u);
                float r1 = h1 - __uint_as_float(ub1 & 0xffff0000u);
                lo[q] = cvt_bf16x2(r0, r1);
            }
        }
    }
}

// ---------------------------------------------------------------------------
// Fused async kernel: one CTA / instrument, 640 threads.
// Warps 0-7: consumers (MMA + W convert). Warps 8-19: producers (conv + W cp.async).
// Decoupled via named-barrier ring (X 4-deep, W f32 4-deep).
// ---------------------------------------------------------------------------
__global__ __launch_bounds__(NTHREADS, 1) void fused_kernel(
    const float* __restrict__ data,
    const float* __restrict__ w1, const float* __restrict__ b1,
    const float* __restrict__ w2, const float* __restrict__ b2,
    const float* __restrict__ wfc,
    const float* __restrict__ bfc,
    float* __restrict__ out)
{
    extern __shared__ char sm[];
    const uint32_t sbase = smem_u32(sm);
    const int i = blockIdx.x;
    const int tid = threadIdx.x;
    const int lane = tid & 31;
    const int wid = tid >> 5;

    // zero bf16-W buffers (pad note rows 88..95 stay zero forever)
    for (int o = tid * 16; o < 2 * WB_STAGE; o += NTHREADS * 16)
        *(uint4*)(sm + WB_OFF + o) = make_uint4(0, 0, 0, 0);
    __syncthreads();

    const float* Wp = wfc + (size_t)i * N_NOTES * FEAT;

    if (tid < 256) {
        // ================= CONSUMERS (warps 0-7) =================
        const int warp_n = wid & 3;
        const int warp_m = wid >> 2;
        const int n0 = warp_n * 24;
        float acc[2][3][4];
#pragma unroll
        for (int mt = 0; mt < 2; ++mt)
#pragma unroll
            for (int nt = 0; nt < 3; ++nt)
#pragma unroll
                for (int r = 0; r < 4; ++r) acc[mt][nt][r] = 0.f;

        const int a_row = lane & 15;
        const int a_colb = (lane >> 4) << 4;
        const int b4_row = (lane & 7) + ((lane >> 4) << 3);
        const int b4_colb = ((lane >> 3) & 1) << 4;
        const int b2_row = lane & 7;
        const int b2_colb = ((lane >> 3) & 1) << 4;

        for (int c = 0; c < NCHUNK; ++c) {
            const int s = c & 3;
            // wait: X stage s filled + W f32 chunk c resident
            BAR_SYNC(FB0 + s, NTHREADS);

            // convert W f32 chunk c -> bf16 hi/lo buffer (c&1)
            {
                const char* src = sm + WF32_OFF + s * WF32_STAGE;
                char* dhi = sm + WB_OFF + (c & 1) * WB_STAGE;
                char* dlo = dhi + WLO_REL;
#pragma unroll
                for (int sh = 0; sh < 5; ++sh) {
                    int idx = tid + sh * 256;
                    if (idx < 1056) {
                        int row = idx / 12, q = idx % 12;
                        float4 v = *(const float4*)(src + idx * 16);
                        unsigned ax = __float_as_uint(v.x), ay = __float_as_uint(v.y);
                        unsigned az = __float_as_uint(v.z), aw = __float_as_uint(v.w);
                        unsigned hi0 = __byte_perm(ax, ay, 0x7632);
                        unsigned hi1 = __byte_perm(az, aw, 0x7632);
                        float rx = v.x - __uint_as_float(ax & 0xffff0000u);
                        float ry = v.y - __uint_as_float(ay & 0xffff0000u);
                        float rz = v.z - __uint_as_float(az & 0xffff0000u);
                        float rw = v.w - __uint_as_float(aw & 0xffff0000u);
                        unsigned lo0 = cvt_bf16x2(rx, ry);
                        unsigned lo1 = cvt_bf16x2(rz, rw);
                        unsigned off = swz(row * 128 + q * 8);
                        *(uint2*)(dhi + off) = make_uint2(hi0, hi1);
                        *(uint2*)(dlo + off) = make_uint2(lo0, lo1);
                    }
                }
            }
            // consumer-only barrier: convert visible to all consumer warps
            BAR_SYNC(CBID, 256);
            // signal: W f32 stage s fully consumed (safe to overwrite)
            BAR_ARRIVE(WD0 + s, NTHREADS);

            // MMA on X[s] and WB[c&1]
            const uint32_t xb = sbase + X_OFF + s * X_STAGE;
            const uint32_t wb = sbase + WB_OFF + (c & 1) * WB_STAGE;
#pragma unroll
            for (int ks = 0; ks < 3; ++ks) {
                const int kb = ks * 32;
                unsigned bh[3][2], bl[3][2];
                unsigned off4 = swz((n0 + b4_row) * 128 + kb + b4_colb);
                ldsm4(&bh[0][0], wb + off4);
                ldsm4(&bl[0][0], wb + WLO_REL + off4);
                unsigned off2 = swz((n0 + 16 + b2_row) * 128 + kb + b2_colb);
                ldsm2(bh[2], wb + off2);
                ldsm2(bl[2], wb + WLO_REL + off2);
#pragma unroll
                for (int mt = 0; mt < 2; ++mt) {
                    unsigned ahi[4], alo[4];
                    unsigned offA = swz(((warp_m * 2 + mt) * 16 + a_row) * 128 + kb + a_colb);
                    ldsm4(ahi, xb + offA);
                    ldsm4(alo, xb + XLO_REL + offA);
#pragma unroll
                    for (int nt = 0; nt < 3; ++nt) {
                        mma_bf16(acc[mt][nt], ahi, bh[nt]);
                        mma_bf16(acc[mt][nt], ahi, bl[nt]);
                        mma_bf16(acc[mt][nt], alo, bh[nt]);
                    }
                }
            }
            // signal: X stage s consumed
            BAR_ARRIVE(EB0 + s, NTHREADS);
        }

        // epilogue: bias + sigmoid + store out[b][i][n]
#pragma unroll
        for (int mt = 0; mt < 2; ++mt) {
            int b0 = (warp_m * 2 + mt) * 16 + (lane >> 2);
#pragma unroll
            for (int nt = 0; nt < 3; ++nt) {
                int n = n0 + nt * 8 + 2 * (lane & 3);
                if (n < N_NOTES) {
                    float bi0 = bfc[i * N_NOTES + n];
                    float bi1 = bfc[i * N_NOTES + n + 1];
                    float s0 = acc[mt][nt][0] + bi0;
                    float s1 = acc[mt][nt][1] + bi1;
                    float s2 = acc[mt][nt][2] + bi0;
                    float s3 = acc[mt][nt][3] + bi1;
                    float2 r0 = make_float2(1.f / (1.f + __expf(-s0)), 1.f / (1.f + __expf(-s1)));
                    float2 r1 = make_float2(1.f / (1.f + __expf(-s2)), 1.f / (1.f + __expf(-s3)));
                    *(float2*)(out + ((size_t)b0 * N_INST + i) * N_NOTES + n) = r0;
                    *(float2*)(out + ((size_t)(b0 + 8) * N_INST + i) * N_NOTES + n) = r1;
                }
            }
        }
    } else {
        // ================= PRODUCERS (warps 8-19) =================
        const int ptid = tid - 256;     // 0..383
        const int s = ptid % 6;         // strip: output cols 8s..8s+7
        const int b = ptid / 6;         // batch 0..63

        float W1[9], W2[9];
#pragma unroll
        for (int k = 0; k < 9; ++k) { W1[k] = w1[i * 9 + k]; W2[k] = w2[i * 9 + k]; }
        const float B1 = b1[i], B2 = b2[i];

        const float* dptr = data + (size_t)b * TLEN * FLEN + 8 * s;
        const unsigned xoff = swz(b * 128 + s * 16);

        float ca[3][10], u[3][8];
#pragma unroll
        for (int k = 0; k < 3; ++k) {
#pragma unroll
            for (int j = 0; j < 10; ++j) ca[k][j] = 0.f;
#pragma unroll
            for (int j = 0; j < 8; ++j) u[k][j] = 0.f;
        }
        unsigned hi[4], lo[4];

        auto prefetchW = [&](int c) {
            const int k0 = c * KC;
            const uint32_t wdst = sbase + WF32_OFF + (c & 3) * WF32_STAGE;
#pragma unroll
            for (int sh = 0; sh < 3; ++sh) {
                int idx = ptid + sh * 384;
                if (idx < 1056)
                    cp16g(wdst + idx * 16, Wp + (size_t)(idx / 12) * FEAT + k0 + (idx % 12) * 4);
            }
            cp_commit();
        };
        auto xstore = [&](int st) {
            uint32_t xa = sbase + X_OFF + st * X_STAGE;
            sts128(xa + xoff, hi[0], hi[1], hi[2], hi[3]);
            sts128(xa + XLO_REL + xoff, lo[0], lo[1], lo[2], lo[3]);
        };

        // prologue: W stages 0,1 in flight; conv rows 0..3
        prefetchW(0);
        prefetchW(1);
        conv_iter<0, 2, 1>(0, false, false, ca, u, dptr, W1, W2, B1, B2, hi, lo);
        conv_iter<1, 0, 2>(1, false, false, ca, u, dptr, W1, W2, B1, B2, hi, lo);
        conv_iter<2, 1, 0>(2, true,  false, ca, u, dptr, W1, W2, B1, B2, hi, lo);
        conv_iter<0, 2, 1>(3, true,  false, ca, u, dptr, W1, W2, B1, B2, hi, lo);

#define PBODY(c, S0, S1, S2) do { \
    if ((c) >= 2) BAR_SYNC(WD0 + (((c) + 2) & 3), NTHREADS); \
    if ((c) + 2 < NCHUNK) prefetchW((c) + 2); \
    if ((c) >= 4) BAR_SYNC(EB0 + ((c) & 3), NTHREADS); \
    conv_iter<S0, S1, S2>((c) + 4, true, true, ca, u, dptr, W1, W2, B1, B2, hi, lo); \
    xstore((c) & 3); \
    if ((c) < NCHUNK - 2)       { CP_WAIT(2); } \
    else if ((c) == NCHUNK - 2) { CP_WAIT(1); } \
    else                        { CP_WAIT(0); } \
    MEMBAR_CTA(); \
    BAR_ARRIVE(FB0 + ((c) & 3), NTHREADS); \
} while (0)

        for (int c0 = 0; c0 < 195; c0 += 3) {
            PBODY(c0 + 0, 1, 0, 2);
            PBODY(c0 + 1, 2, 1, 0);
            PBODY(c0 + 2, 0, 2, 1);
        }
        PBODY(195, 1, 0, 2);
        PBODY(196, 2, 1, 0);
#undef PBODY
    }
}

// ---------------------------------------------------------------------------
extern "C" void kernel_launch(void* const* d_in, const int* in_sizes, int n_in,
                              void* d_out, int out_size)
{
    const float* data = (const float*)d_in[0];
    const float* w1   = (const float*)d_in[1];
    const float* b1   = (const float*)d_in[2];
    const float* w2   = (const float*)d_in[3];
    const float* b2   = (const float*)d_in[4];
    const float* wfc  = (const float*)d_in[5];
    const float* bfc  = (const float*)d_in[6];
    float* out = (float*)d_out;

    cudaFuncSetAttribute(fused_kernel, cudaFuncAttributeMaxDynamicSharedMemorySize, SMEM_TOTAL);
    fused_kernel<<<N_INST, NTHREADS, SMEM_TOTAL>>>(data, w1, b1, w2, b2, wfc, bfc, out);
}